// round 13
// baseline (speedup 1.0000x reference)
#include <cuda_runtime.h>
#include <cuda_fp16.h>
#include <stdint.h>
#include <math.h>

// ---------------- problem constants ------------------------------------------
#define NTH   512
#define T_LEN 128
#define OBS   32
#define CC    33
#define HID   64
#define WID   128
#define FOUT  2112

#define ACT_NONE 0
#define ACT_RELU 1
#define ACT_SP   2

// fWo fp16, mma.m16n8k16 A-fragment layout (verified in R12 prep):
// uint4 idx = ((rank*66 + t)*8 + q)*32 + lane; tile t = rows [(rank*66+t)*16, +16)
__device__ __align__(16) uint4 g_fWoA[33792];

// hidden-chain weights as half2, column layout (R7/R11-proven):
__device__ __align__(16) __half2 g_fWhH2[3 * 64 * WID];
__device__ __align__(16) __half2 g_fW0H2[32 * WID];

__global__ void prep_fwo(const float* __restrict__ fWo) {
    int idx = blockIdx.x * blockDim.x + threadIdx.x;
    if (idx >= 33792) return;
    int l = idx & 31;
    int rest = idx >> 5;
    int q = rest & 7;
    int rt = rest >> 3;           // rank*66 + t (0..131)
    int row_base = rt * 16;
    int r0 = l >> 2;
    int c0 = (l & 3) * 2;
    int k0 = q * 16;
    auto W = [&](int r, int kk) -> uint32_t {
        float v = fWo[(size_t)(row_base + r) * WID + k0 + kk];
        return (uint32_t)__half_as_ushort(__float2half(v));
    };
    uint4 out;
    out.x = W(r0,     c0)     | (W(r0,     c0 + 1) << 16);
    out.y = W(r0 + 8, c0)     | (W(r0 + 8, c0 + 1) << 16);
    out.z = W(r0,     c0 + 8) | (W(r0,     c0 + 9) << 16);
    out.w = W(r0 + 8, c0 + 8) | (W(r0 + 8, c0 + 9) << 16);
    g_fWoA[idx] = out;
}

// R7-proven prep: column-major half2 packing for hidden layers
__global__ void prep_h2(const float* __restrict__ fWh, const float* __restrict__ fW0) {
    int idx = blockIdx.x * blockDim.x + threadIdx.x;
    if (idx < 3 * 64 * WID) {
        int o = idx & 127;
        int t = idx >> 7;
        int kp = t & 63;
        int l = t >> 6;
        const float* row = fWh + ((size_t)(l * WID + o)) * WID;
        g_fWhH2[idx] = __floats2half2_rn(row[2 * kp], row[2 * kp + 1]);
    } else if (idx < 3 * 64 * WID + 32 * WID) {
        int i2 = idx - 3 * 64 * WID;
        int o = i2 & 127;
        int kp = i2 >> 7;
        const float* row = fW0 + (size_t)o * HID;
        g_fW0H2[i2] = __floats2half2_rn(row[2 * kp], row[2 * kp + 1]);
    }
}

// ---------------- small device helpers ---------------------------------------
__device__ __forceinline__ uint32_t s2u(const void* p) {
    return (uint32_t)__cvta_generic_to_shared(p);
}
__device__ __forceinline__ void bar_init(uint32_t addr, uint32_t count) {
    asm volatile("mbarrier.init.shared.b64 [%0], %1;" :: "r"(addr), "r"(count) : "memory");
}
__device__ __forceinline__ void bar_arrive_peer(uint32_t local_bar, uint32_t peer) {
    asm volatile(
        "{\n\t.reg .b32 ra;\n\t"
        "mapa.shared::cluster.u32 ra, %0, %1;\n\t"
        "mbarrier.arrive.release.cluster.shared::cluster.b64 _, [ra];\n\t}"
        :: "r"(local_bar), "r"(peer) : "memory");
}
__device__ __forceinline__ void st_peer_f32(uint32_t local_addr, uint32_t peer, float v) {
    asm volatile(
        "{\n\t.reg .b32 ra;\n\t"
        "mapa.shared::cluster.u32 ra, %0, %1;\n\t"
        "st.shared::cluster.f32 [ra], %2;\n\t}"
        :: "r"(local_addr), "r"(peer), "f"(v) : "memory");
}
__device__ __forceinline__ void bar_wait(uint32_t addr, uint32_t parity) {
    asm volatile(
        "{\n\t.reg .pred P;\n"
        "W%=:\n\t"
        "mbarrier.try_wait.parity.acquire.cluster.shared::cta.b64 P, [%0], %1, 0x989680;\n\t"
        "@!P bra W%=;\n\t}"
        :: "r"(addr), "r"(parity) : "memory");
}
__device__ __forceinline__ uint32_t ctarank() {
    uint32_t r;
    asm("mov.u32 %0, %%cluster_ctarank;" : "=r"(r));
    return r;
}

__device__ __forceinline__ float softplus_f(float x) {
    return fmaxf(x, 0.f) + __logf(1.f + __expf(-fabsf(x)));
}
__device__ __forceinline__ float tanh_f(float x) {
    float e = __expf(-2.0f * fabsf(x));
    float t = __fdividef(1.0f - e, 1.0f + e);
    return copysignf(t, x);
}

// m16n8k16 f16 x f16 -> f32 accumulate
__device__ __forceinline__ void mma16816(float d[4], uint4 a, uint2 b) {
    asm volatile(
        "mma.sync.aligned.m16n8k16.row.col.f32.f16.f16.f32 "
        "{%0,%1,%2,%3}, {%4,%5,%6,%7}, {%8,%9}, {%0,%1,%2,%3};"
        : "+f"(d[0]), "+f"(d[1]), "+f"(d[2]), "+f"(d[3])
        : "r"(a.x), "r"(a.y), "r"(a.z), "r"(a.w), "r"(b.x), "r"(b.y));
}

// R11-proven hidden layer; optionally mirrors output to fp16 (for fWo mma B)
template <int NKP, int ACT, bool WRITE_XH>
__device__ __forceinline__ void layer_h2(const __half2* __restrict__ Wc,
                                         const float* __restrict__ x,
                                         float biasv,
                                         float* __restrict__ outv,
                                         __half* __restrict__ xh,
                                         float* __restrict__ s_part) {
    const int tid = threadIdx.x;
    const int o = tid & 127;
    const int p = tid >> 7;
    constexpr int JP = NKP / 4;
    const __half2* col = Wc + JP * p * 128 + o;
    const float4* x4 = (const float4*)x + (JP / 2) * p;
    float acc = 0.f;
#pragma unroll
    for (int m = 0; m < JP / 2; m++) {
        float4 xv = x4[m];
        float2 wfa = __half22float2(col[(2 * m) * 128]);
        float2 wfb = __half22float2(col[(2 * m + 1) * 128]);
        acc = fmaf(wfa.x, xv.x, acc);
        acc = fmaf(wfa.y, xv.y, acc);
        acc = fmaf(wfb.x, xv.z, acc);
        acc = fmaf(wfb.y, xv.w, acc);
    }
    s_part[tid] = acc;
    __syncthreads();
    if (tid < 128) {
        float v = s_part[tid] + s_part[tid + 128] + s_part[tid + 256]
                + s_part[tid + 384] + biasv;
        if (ACT == ACT_RELU) v = fmaxf(v, 0.f);
        if (ACT == ACT_SP)   v = softplus_f(v);
        outv[tid] = v;
        if (WRITE_XH) xh[tid] = __float2half(v);
    }
    __syncthreads();
}

// full-width fp32 warp-coop matvec (cold paths: init MLP, readout)
template <int OPW, int I, int ACT>
__device__ __forceinline__ void mvw(const float* __restrict__ W,
                                    const float* __restrict__ x,
                                    const float* __restrict__ bias,
                                    float* __restrict__ outv) {
    constexpr int NJ = (I + 31) / 32;
    const int w = threadIdx.x >> 5;
    const int l = threadIdx.x & 31;
    float xr[NJ];
#pragma unroll
    for (int j = 0; j < NJ; j++) {
        int k = l + 32 * j;
        xr[j] = (k < I) ? x[k] : 0.f;
    }
    float acc[OPW];
#pragma unroll
    for (int oo = 0; oo < OPW; oo++) {
        const float* row = W + (w * OPW + oo) * I;
        float a = 0.f;
#pragma unroll
        for (int j = 0; j < NJ; j++) {
            int k = l + 32 * j;
            if (k < I) a = fmaf(row[k], xr[j], a);
        }
        acc[oo] = a;
    }
#pragma unroll
    for (int d = 16; d >= 1; d >>= 1)
#pragma unroll
        for (int oo = 0; oo < OPW; oo++)
            acc[oo] += __shfl_xor_sync(0xFFFFFFFFu, acc[oo], d);
    if (l < OPW) {
        float v = acc[l] + bias[w * OPW + l];
        if (ACT == ACT_RELU) v = fmaxf(v, 0.f);
        if (ACT == ACT_SP)   v = softplus_f(v);
        outv[w * OPW + l] = v;
    }
}

__global__ void __launch_bounds__(NTH, 1) __cluster_dims__(2, 1, 1)
ncde_main(const float* __restrict__ ts, const float* __restrict__ ys,
          const float* __restrict__ iW0, const float* __restrict__ ib0,
          const float* __restrict__ iWh, const float* __restrict__ ibh,
          const float* __restrict__ iWo, const float* __restrict__ ibo,
          const float* __restrict__ fb0g, const float* __restrict__ fbhg,
          const float* __restrict__ fbo, const float* __restrict__ lW,
          const float* __restrict__ lb, float* __restrict__ out) {
    extern __shared__ __align__(16) char smraw[];
    __half2* s_Wh = (__half2*)(smraw + 16);          // 98304 B
    __half*  s_xh = (__half*)(s_Wh + 3 * 64 * WID);  // 256 B
    float* s_tys  = (float*)(s_xh + 128);            // 4224 floats
    float* s_fboH = s_tys + T_LEN * CC;              // 1056
    float* s_P    = s_fboH + 1056;                   // 1056
    float* s_part = s_P + 1056;                      // 512
    float* s_fbh  = s_part + NTH;                    // 384
    float* s_fb0  = s_fbh + 3 * WID;                 // 128
    float* s_ha   = s_fb0 + WID;                     // 128
    float* s_hb   = s_ha + WID;                      // 128
    float* s_y    = s_hb + WID;                      // 64
    float* s_yt   = s_y + HID;                       // 64
    float* s_ks   = s_yt + HID;                      // 64
    float* s_f    = s_ks + HID;                      // 64
    float* s_xd   = s_f + HID;                       // 36
    float* s_d0   = s_xd + 36;                       // 36
    float* s_cc   = s_d0 + 36;                       // 36
    float* s_bb   = s_cc + 36;                       // 36

    const int tid = threadIdx.x;
    const int b = blockIdx.x >> 1;
    const int rank = (int)ctarank();
    const uint32_t peer = (uint32_t)(rank ^ 1);
    const int wrp = tid >> 5;
    const int lane = tid & 31;

    const uint32_t barF = s2u(smraw);
    const uint32_t u_f  = s2u(s_f);

    if (tid == 0) bar_init(barF, 32);
    __syncthreads();
    asm volatile("barrier.cluster.arrive.aligned;" ::: "memory");
    asm volatile("barrier.cluster.wait.aligned;" ::: "memory");

    // --- stage fp16 fWh weights + tys + biases ----------------------------------
    {
        const uint4* src = (const uint4*)g_fWhH2;
        uint4* dst = (uint4*)s_Wh;
        for (int i = tid; i < 3 * 64 * WID / 4; i += NTH) dst[i] = src[i];
    }
    for (int i = tid; i < T_LEN * CC; i += NTH) {
        int t = i / CC, c = i - t * CC;
        s_tys[i] = (c == 0) ? ts[t] : ys[(b * T_LEN + t) * OBS + (c - 1)];
    }
    for (int i = tid; i < 32 * CC; i += NTH) s_fboH[i] = fbo[rank * 32 * CC + i];
    if (tid < 3 * WID) s_fbh[tid] = fbhg[tid];
    if (tid < WID)     s_fb0[tid] = fb0g[tid];
    __syncthreads();

    // hoisted loop-invariant biases (registers)
    const int o127 = tid & 127;
    const float rb0  = s_fb0[o127];
    const float rbh1 = s_fbh[o127];
    const float rbh2 = s_fbh[WID + o127];
    const float rbh3 = s_fbh[2 * WID + o127];

    int phF = 0;

    // --- initial MLP (redundant in both CTAs, fp32, cold) -> y0 ----------------
    mvw<8, CC, ACT_RELU>(iW0, s_tys, ib0, s_ha);                        __syncthreads();
    mvw<8, WID, ACT_RELU>(iWh,         s_ha, ibh,           s_hb);      __syncthreads();
    mvw<8, WID, ACT_RELU>(iWh + 16384, s_hb, ibh + WID,     s_ha);      __syncthreads();
    mvw<8, WID, ACT_RELU>(iWh + 32768, s_ha, ibh + 2 * WID, s_hb);      __syncthreads();
    mvw<4, WID, ACT_NONE>(iWo, s_hb, ibo, s_y);                         __syncthreads();

    if (rank == 0) mvw<2, HID, ACT_NONE>(lW, s_y, lb, out + (size_t)(b * T_LEN) * OBS);

    // fWo mma fragment base for this CTA (per-lane)
    const uint4* WA = g_fWoA + (size_t)rank * 66 * 256 + lane;
    const uint32_t* xh32 = (const uint32_t*)s_xh;

    // --- vector field -----------------------------------------------------------
    auto vf = [&](float s, const float* __restrict__ yy) {
        if (tid < CC)
            s_xd[tid] = s_d0[tid] + 2.f * s_cc[tid] * s + 3.f * s_bb[tid] * s * s;
        // hidden chain: R11-proven math; layer-0 weights streamed from global
        layer_h2<32, ACT_SP, false>(g_fW0H2, yy, rb0, s_ha, s_xh, s_part);
        layer_h2<64, ACT_SP, false>(s_Wh,             s_ha, rbh1, s_hb, s_xh, s_part);
        layer_h2<64, ACT_SP, false>(s_Wh + 64 * WID,  s_hb, rbh2, s_ha, s_xh, s_part);
        layer_h2<64, ACT_SP, true >(s_Wh + 128 * WID, s_ha, rbh3, s_hb, s_xh, s_part);

        // ---- fWo: tensor-core matvec (m16n8k16, fp32 accumulate) ----
        {
            uint2 Bq[8];
#pragma unroll
            for (int q = 0; q < 8; q++) {
                Bq[q].x = xh32[q * 8 + (lane & 3)];
                Bq[q].y = xh32[q * 8 + 4 + (lane & 3)];
            }
            auto do_tile = [&](int t) {
                float D[4] = {0.f, 0.f, 0.f, 0.f};
                const uint4* wp = WA + t * 256;
#pragma unroll
                for (int q = 0; q < 8; q++)
                    mma16816(D, wp[q * 32], Bq[q]);
                if ((lane & 3) == 0) {
                    int g = lane >> 2;
                    int o0 = t * 16 + g;
                    int o1 = o0 + 8;
                    s_P[o0] = tanh_f(D[0] + s_fboH[o0]) * s_xd[o0 % CC];
                    s_P[o1] = tanh_f(D[2] + s_fboH[o1]) * s_xd[o1 % CC];
                }
            };
            do_tile(wrp);
            do_tile(wrp + 16);
            do_tile(wrp + 32);
            do_tile(wrp + 48);
            if (wrp < 2) do_tile(64 + wrp);
            __syncthreads();

            // contraction: 256 threads, 8 per h row
            if (tid < 256) {
                int h = tid >> 3, j = tid & 7;
                const float* pr = s_P + h * CC;
                float v = pr[j] + pr[j + 8] + pr[j + 16] + pr[j + 24];
                if (j == 0) v += pr[32];
                v += __shfl_xor_sync(0xFFFFFFFFu, v, 1);
                v += __shfl_xor_sync(0xFFFFFFFFu, v, 2);
                v += __shfl_xor_sync(0xFFFFFFFFu, v, 4);
                if (j == 0) {
                    int hg = rank * 32 + h;
                    s_f[hg] = v;
                    st_peer_f32(u_f + hg * 4, peer, v);
                    bar_arrive_peer(barF, peer);
                }
            }
            __syncthreads();
            bar_wait(barF, phF & 1); phF++;
        }
    };

    // --- interval scan + RK4 -----------------------------------------------------
    for (int iv = 0; iv < T_LEN - 1; iv++) {
        float dti = s_tys[(iv + 1) * CC] - s_tys[iv * CC];
        if (tid < CC) {
            float di = (s_tys[(iv + 1) * CC + tid] - s_tys[iv * CC + tid]) / dti;
            float d0v;
            if (iv == 0) {
                d0v = di;
            } else {
                float dtm = s_tys[iv * CC] - s_tys[(iv - 1) * CC];
                d0v = (s_tys[iv * CC + tid] - s_tys[(iv - 1) * CC + tid]) / dtm;
            }
            float d1v = di;
            s_d0[tid] = d0v;
            s_cc[tid] = (3.f * di - 2.f * d0v - d1v) / dti;
            s_bb[tid] = (d0v + d1v - 2.f * di) / (dti * dti);
        }
        __syncthreads();

        float hsub = dti * 0.25f;
#pragma unroll 1
        for (int sub = 0; sub < 4; sub++) {
            float s0 = hsub * (float)sub;
            vf(s0, s_y);
            if (tid < HID) {
                float k1 = s_f[tid];
                s_ks[tid] = k1;
                s_yt[tid] = fmaf(0.5f * hsub, k1, s_y[tid]);
            }
            __syncthreads();
            vf(s0 + 0.5f * hsub, s_yt);
            if (tid < HID) {
                float k2 = s_f[tid];
                s_ks[tid] += 2.f * k2;
                s_yt[tid] = fmaf(0.5f * hsub, k2, s_y[tid]);
            }
            __syncthreads();
            vf(s0 + 0.5f * hsub, s_yt);
            if (tid < HID) {
                float k3 = s_f[tid];
                s_ks[tid] += 2.f * k3;
                s_yt[tid] = fmaf(hsub, k3, s_y[tid]);
            }
            __syncthreads();
            vf(s0 + hsub, s_yt);
            if (tid < HID) {
                s_y[tid] = fmaf(hsub * (1.f / 6.f), s_ks[tid] + s_f[tid], s_y[tid]);
            }
            __syncthreads();
        }

        if (rank == 0) mvw<2, HID, ACT_NONE>(lW, s_y, lb, out + (size_t)(b * T_LEN + iv + 1) * OBS);
    }

    asm volatile("barrier.cluster.arrive.aligned;" ::: "memory");
    asm volatile("barrier.cluster.wait.aligned;" ::: "memory");
}

// ---------------- launch --------------------------------------------------------
static const int SMEM_BYTES = 16
    + (3 * 64 * WID) * 4                        // fWh half2 weights
    + 256                                        // s_xh
    + (T_LEN * CC + 1056 + 1056 + NTH + 3 * WID + WID + 2 * WID + 4 * HID + 4 * 36) * 4;

extern "C" void kernel_launch(void* const* d_in, const int* in_sizes, int n_in,
                              void* d_out, int out_size) {
    const float* ts  = (const float*)d_in[0];
    const float* ys  = (const float*)d_in[1];
    const float* iW0 = (const float*)d_in[2];
    const float* ib0 = (const float*)d_in[3];
    const float* iWh = (const float*)d_in[4];
    const float* ibh = (const float*)d_in[5];
    const float* iWo = (const float*)d_in[6];
    const float* ibo = (const float*)d_in[7];
    const float* fW0 = (const float*)d_in[8];
    const float* fb0 = (const float*)d_in[9];
    const float* fWh = (const float*)d_in[10];
    const float* fbh = (const float*)d_in[11];
    const float* fWo = (const float*)d_in[12];
    const float* fbo = (const float*)d_in[13];
    const float* lW  = (const float*)d_in[14];
    const float* lb  = (const float*)d_in[15];
    float* out = (float*)d_out;

    cudaFuncSetAttribute(ncde_main, cudaFuncAttributeMaxDynamicSharedMemorySize, SMEM_BYTES);

    prep_fwo<<<132, 256>>>(fWo);
    prep_h2<<<112, 256>>>(fWh, fW0);
    ncde_main<<<128, NTH, SMEM_BYTES>>>(ts, ys, iW0, ib0, iWh, ibh, iWo, ibo,
                                        fb0, fbh, fbo, lW, lb, out);
}

// round 15
// speedup vs baseline: 1.2530x; 1.2530x over previous
#include <cuda_runtime.h>
#include <cuda_fp16.h>
#include <stdint.h>
#include <math.h>

// ---------------- problem constants ------------------------------------------
#define NTH   512
#define T_LEN 128
#define OBS   32
#define CC    33
#define HID   64
#define WID   128
#define FOUT  2112

#define ACT_NONE 0
#define ACT_RELU 1
#define ACT_SP   2

// fWo fp16, (h, channel-pair) warp-interleaved layout (R7/R11-proven).
__device__ __align__(16) __half g_fWoH[FOUT * WID];   // 33792 uint4

// hidden-chain weights as half2, column layout (R7/R11-proven):
__device__ __align__(16) __half2 g_fWhH2[3 * 64 * WID];
__device__ __align__(16) __half2 g_fW0H2[32 * WID];

// per-CTA tys scratch (128 CTAs x 4224 floats) -- moved out of smem (R15)
__device__ float g_tys[128 * T_LEN * CC];

__global__ void prep_fwo(const float* __restrict__ fWo) {
    int idx = blockIdx.x * blockDim.x + threadIdx.x;
    if (idx >= 33792) return;
    __half hv[8];
    if (idx < 32768) {
        int l = idx & 31;
        int t = idx >> 5;
        int chI = t & 1;  t >>= 1;
        int kc = t & 15;  t >>= 4;
        int w = t & 15;
        int r = t >> 4;
        int h = r * 32 + w * 2 + (l >> 4);
        int p = l & 15;
        int c = chI ? (p + 16) : p;
#pragma unroll
        for (int j = 0; j < 8; j++)
            hv[j] = __float2half(fWo[(h * CC + c) * WID + kc * 8 + j]);
    } else {
        int i2 = idx - 32768;
        int l = i2 & 31;
        int rw = i2 >> 5;
        int w = rw & 15;
        int r = rw >> 4;
        int h = r * 32 + w * 2 + (l >> 4);
        int p = l & 15;
#pragma unroll
        for (int j = 0; j < 8; j++)
            hv[j] = __float2half(fWo[(h * CC + 32) * WID + p * 8 + j]);
    }
    ((uint4*)g_fWoH)[idx] = *(const uint4*)hv;
}

// R7-proven prep: column-major half2 packing
__global__ void prep_h2(const float* __restrict__ fWh, const float* __restrict__ fW0) {
    int idx = blockIdx.x * blockDim.x + threadIdx.x;
    if (idx < 3 * 64 * WID) {
        int o = idx & 127;
        int t = idx >> 7;
        int kp = t & 63;
        int l = t >> 6;
        const float* row = fWh + ((size_t)(l * WID + o)) * WID;
        g_fWhH2[idx] = __floats2half2_rn(row[2 * kp], row[2 * kp + 1]);
    } else if (idx < 3 * 64 * WID + 32 * WID) {
        int i2 = idx - 3 * 64 * WID;
        int o = i2 & 127;
        int kp = i2 >> 7;
        const float* row = fW0 + (size_t)o * HID;
        g_fW0H2[i2] = __floats2half2_rn(row[2 * kp], row[2 * kp + 1]);
    }
}

// ---------------- small device helpers ---------------------------------------
__device__ __forceinline__ uint32_t s2u(const void* p) {
    return (uint32_t)__cvta_generic_to_shared(p);
}
__device__ __forceinline__ void bar_init(uint32_t addr, uint32_t count) {
    asm volatile("mbarrier.init.shared.b64 [%0], %1;" :: "r"(addr), "r"(count) : "memory");
}
__device__ __forceinline__ void bar_arrive_peer(uint32_t local_bar, uint32_t peer) {
    asm volatile(
        "{\n\t.reg .b32 ra;\n\t"
        "mapa.shared::cluster.u32 ra, %0, %1;\n\t"
        "mbarrier.arrive.release.cluster.shared::cluster.b64 _, [ra];\n\t}"
        :: "r"(local_bar), "r"(peer) : "memory");
}
__device__ __forceinline__ void st_peer_f32(uint32_t local_addr, uint32_t peer, float v) {
    asm volatile(
        "{\n\t.reg .b32 ra;\n\t"
        "mapa.shared::cluster.u32 ra, %0, %1;\n\t"
        "st.shared::cluster.f32 [ra], %2;\n\t}"
        :: "r"(local_addr), "r"(peer), "f"(v) : "memory");
}
__device__ __forceinline__ void bar_wait(uint32_t addr, uint32_t parity) {
    asm volatile(
        "{\n\t.reg .pred P;\n"
        "W%=:\n\t"
        "mbarrier.try_wait.parity.acquire.cluster.shared::cta.b64 P, [%0], %1, 0x989680;\n\t"
        "@!P bra W%=;\n\t}"
        :: "r"(addr), "r"(parity) : "memory");
}
__device__ __forceinline__ uint32_t ctarank() {
    uint32_t r;
    asm("mov.u32 %0, %%cluster_ctarank;" : "=r"(r));
    return r;
}

__device__ __forceinline__ float softplus_f(float x) {
    return fmaxf(x, 0.f) + __logf(1.f + __expf(-fabsf(x)));
}
__device__ __forceinline__ float tanh_f(float x) {
    float e = __expf(-2.0f * fabsf(x));
    float t = __fdividef(1.0f - e, 1.0f + e);
    return copysignf(t, x);
}
// fp32 dot of 8 fp16 weights against 8 fp32 activations (R7-exact)
__device__ __forceinline__ float dot8(uint4 wv, float4 xa, float4 xb, float acc) {
    const __half2* hh = (const __half2*)&wv;
    float2 f0 = __half22float2(hh[0]);
    float2 f1 = __half22float2(hh[1]);
    float2 f2 = __half22float2(hh[2]);
    float2 f3 = __half22float2(hh[3]);
    acc = fmaf(f0.x, xa.x, acc); acc = fmaf(f0.y, xa.y, acc);
    acc = fmaf(f1.x, xa.z, acc); acc = fmaf(f1.y, xa.w, acc);
    acc = fmaf(f2.x, xb.x, acc); acc = fmaf(f2.y, xb.y, acc);
    acc = fmaf(f3.x, xb.z, acc); acc = fmaf(f3.y, xb.w, acc);
    return acc;
}

// R11-proven hidden layer (column-layout fp16 weights, fp32 x/accum)
template <int NKP, int ACT>
__device__ __forceinline__ void layer_h2(const __half2* __restrict__ Wc,
                                         const float* __restrict__ x,
                                         float biasv,
                                         float* __restrict__ outv,
                                         float* __restrict__ s_part) {
    const int tid = threadIdx.x;
    const int o = tid & 127;
    const int p = tid >> 7;          // 0..3
    constexpr int JP = NKP / 4;      // half2 per thread
    const __half2* col = Wc + JP * p * 128 + o;
    const float4* x4 = (const float4*)x + (JP / 2) * p;
    float acc = 0.f;
#pragma unroll
    for (int m = 0; m < JP / 2; m++) {
        float4 xv = x4[m];
        float2 wfa = __half22float2(col[(2 * m) * 128]);
        float2 wfb = __half22float2(col[(2 * m + 1) * 128]);
        acc = fmaf(wfa.x, xv.x, acc);
        acc = fmaf(wfa.y, xv.y, acc);
        acc = fmaf(wfb.x, xv.z, acc);
        acc = fmaf(wfb.y, xv.w, acc);
    }
    s_part[tid] = acc;
    __syncthreads();
    if (tid < 128) {
        float v = s_part[tid] + s_part[tid + 128] + s_part[tid + 256]
                + s_part[tid + 384] + biasv;
        if (ACT == ACT_RELU) v = fmaxf(v, 0.f);
        if (ACT == ACT_SP)   v = softplus_f(v);
        outv[tid] = v;
    }
    __syncthreads();
}

// full-width fp32 warp-coop matvec (cold paths: init MLP, readout)
template <int OPW, int I, int ACT>
__device__ __forceinline__ void mvw(const float* __restrict__ W,
                                    const float* __restrict__ x,
                                    const float* __restrict__ bias,
                                    float* __restrict__ outv) {
    constexpr int NJ = (I + 31) / 32;
    const int w = threadIdx.x >> 5;
    const int l = threadIdx.x & 31;
    float xr[NJ];
#pragma unroll
    for (int j = 0; j < NJ; j++) {
        int k = l + 32 * j;
        xr[j] = (k < I) ? x[k] : 0.f;
    }
    float acc[OPW];
#pragma unroll
    for (int oo = 0; oo < OPW; oo++) {
        const float* row = W + (w * OPW + oo) * I;
        float a = 0.f;
#pragma unroll
        for (int j = 0; j < NJ; j++) {
            int k = l + 32 * j;
            if (k < I) a = fmaf(row[k], xr[j], a);
        }
        acc[oo] = a;
    }
#pragma unroll
    for (int d = 16; d >= 1; d >>= 1)
#pragma unroll
        for (int oo = 0; oo < OPW; oo++)
            acc[oo] += __shfl_xor_sync(0xFFFFFFFFu, acc[oo], d);
    if (l < OPW) {
        float v = acc[l] + bias[w * OPW + l];
        if (ACT == ACT_RELU) v = fmaxf(v, 0.f);
        if (ACT == ACT_SP)   v = softplus_f(v);
        outv[w * OPW + l] = v;
    }
}

__global__ void __launch_bounds__(NTH, 1) __cluster_dims__(2, 1, 1)
ncde_main(const float* __restrict__ ts, const float* __restrict__ ys,
          const float* __restrict__ iW0, const float* __restrict__ ib0,
          const float* __restrict__ iWh, const float* __restrict__ ibh,
          const float* __restrict__ iWo, const float* __restrict__ ibo,
          const float* __restrict__ fb0g, const float* __restrict__ fbhg,
          const float* __restrict__ fbo, const float* __restrict__ lW,
          const float* __restrict__ lb, float* __restrict__ out) {
    extern __shared__ __align__(16) char smraw[];
    __half2* s_Wh = (__half2*)(smraw + 16);          // 98304 B
    __half2* s_W0 = s_Wh + 3 * 64 * WID;             // 16384 B
    float* s_fboH = (float*)(s_W0 + 32 * WID);       // 1056 floats
    float* s_part = s_fboH + 32 * CC;                // 512
    float* s_fbh  = s_part + NTH;                    // 384
    float* s_fb0  = s_fbh + 3 * WID;                 // 128
    float* s_ha   = s_fb0 + WID;                     // 128
    float* s_hb   = s_ha + WID;                      // 128
    float* s_y    = s_hb + WID;                      // 64
    float* s_yt   = s_y + HID;                       // 64
    float* s_ks   = s_yt + HID;                      // 64
    float* s_f    = s_ks + HID;                      // 64
    float* s_xd   = s_f + HID;                       // 36
    float* s_d0   = s_xd + 36;                       // 36
    float* s_cc   = s_d0 + 36;                       // 36
    float* s_bb   = s_cc + 36;                       // 36

    const int tid = threadIdx.x;
    const int b = blockIdx.x >> 1;
    const int rank = (int)ctarank();
    const uint32_t peer = (uint32_t)(rank ^ 1);
    const int wrp = tid >> 5;
    const int lane = tid & 31;
    const int hl = tid >> 4;          // 0..31 local h row (fWo block)
    const int p16 = tid & 15;         // channel id (fWo block)

    float* tysb = g_tys + (size_t)blockIdx.x * (T_LEN * CC);

    const uint32_t barF = s2u(smraw);
    const uint32_t u_f  = s2u(s_f);

    if (tid == 0) bar_init(barF, 32);
    __syncthreads();
    asm volatile("barrier.cluster.arrive.aligned;" ::: "memory");
    asm volatile("barrier.cluster.wait.aligned;" ::: "memory");

    // --- stage fp16 hidden weights + tys(global) + biases ------------------------
    {
        const uint4* src = (const uint4*)g_fWhH2;
        uint4* dst = (uint4*)s_Wh;
        for (int i = tid; i < 3 * 64 * WID / 4; i += NTH) dst[i] = src[i];
        const uint4* s2 = (const uint4*)g_fW0H2;
        uint4* d2 = (uint4*)s_W0;
        for (int i = tid; i < 32 * WID / 4; i += NTH) d2[i] = s2[i];
    }
    for (int i = tid; i < T_LEN * CC; i += NTH) {
        int t = i / CC, c = i - t * CC;
        tysb[i] = (c == 0) ? ts[t] : ys[(b * T_LEN + t) * OBS + (c - 1)];
    }
    for (int i = tid; i < 32 * CC; i += NTH) s_fboH[i] = fbo[rank * 32 * CC + i];
    if (tid < 3 * WID) s_fbh[tid] = fbhg[tid];
    if (tid < WID)     s_fb0[tid] = fb0g[tid];
    __syncthreads();
    // ensure tys writes visible before any thread of this CTA reads them
    __threadfence();
    __syncthreads();

    // hoisted loop-invariant biases (registers)
    const int o127 = tid & 127;
    const float rb0  = s_fb0[o127];
    const float rbh1 = s_fbh[o127];
    const float rbh2 = s_fbh[WID + o127];
    const float rbh3 = s_fbh[2 * WID + o127];
    const float fb_a = s_fboH[hl * CC + p16];
    const float fb_b = s_fboH[hl * CC + p16 + 16];
    const float fb_c = s_fboH[hl * CC + 32];

    int phF = 0;

    // --- initial MLP (redundant in both CTAs, fp32, cold) -> y0 ----------------
    mvw<8, CC, ACT_RELU>(iW0, tysb, ib0, s_ha);                         __syncthreads();
    mvw<8, WID, ACT_RELU>(iWh,         s_ha, ibh,           s_hb);      __syncthreads();
    mvw<8, WID, ACT_RELU>(iWh + 16384, s_hb, ibh + WID,     s_ha);      __syncthreads();
    mvw<8, WID, ACT_RELU>(iWh + 32768, s_ha, ibh + 2 * WID, s_hb);      __syncthreads();
    mvw<4, WID, ACT_NONE>(iWo, s_hb, ibo, s_y);                         __syncthreads();

    if (rank == 0) mvw<2, HID, ACT_NONE>(lW, s_y, lb, out + (size_t)(b * T_LEN) * OBS);

    // fWo pointers for this thread (R7/R11-proven)
    const uint4* W1  = ((const uint4*)g_fWoH) + (size_t)(rank * 16 + wrp) * 1024 + lane;
    const uint4* W2p = ((const uint4*)g_fWoH) + 32768 + (size_t)(rank * 16 + wrp) * 32 + lane;
    const int hg = rank * 32 + hl;

    // --- vector field -----------------------------------------------------------
    auto vf = [&](float s, const float* __restrict__ yy) {
        if (tid < CC)
            s_xd[tid] = s_d0[tid] + 2.f * s_cc[tid] * s + 3.f * s_bb[tid] * s * s;
        // hidden chain (R11-proven)
        layer_h2<32, ACT_SP>(s_W0, yy, rb0, s_ha, s_part);
        layer_h2<64, ACT_SP>(s_Wh,             s_ha, rbh1, s_hb, s_part);
        layer_h2<64, ACT_SP>(s_Wh + 64 * WID,  s_hb, rbh2, s_ha, s_part);
        layer_h2<64, ACT_SP>(s_Wh + 128 * WID, s_ha, rbh3, s_hb, s_part);

        // ---- fWo (this CTA's 32 h rows): R11 channel-pair scheme ----
        {
            const float4* hb4 = (const float4*)s_hb;
            float z0a = 0.f, z0b = 0.f, z1a = 0.f, z1b = 0.f;
#pragma unroll
            for (int kc = 0; kc < 16; kc += 2) {
                float4 xa0 = hb4[kc * 2],     xb0 = hb4[kc * 2 + 1];
                float4 xa1 = hb4[kc * 2 + 2], xb1 = hb4[kc * 2 + 3];
                z0a = dot8(W1[kc * 64],      xa0, xb0, z0a);
                z1a = dot8(W1[kc * 64 + 32], xa0, xb0, z1a);
                z0b = dot8(W1[kc * 64 + 64], xa1, xb1, z0b);
                z1b = dot8(W1[kc * 64 + 96], xa1, xb1, z1b);
            }
            float z0 = z0a + z0b;
            float z1 = z1a + z1b;
            float z2 = dot8(*W2p, hb4[p16 * 2], hb4[p16 * 2 + 1], 0.f);

            float part = tanh_f(z0 + fb_a) * s_xd[p16];
            part = fmaf(tanh_f(z1 + fb_b), s_xd[p16 + 16], part);
#pragma unroll
            for (int d = 1; d <= 8; d <<= 1) {
                part += __shfl_xor_sync(0xFFFFFFFFu, part, d);
                z2   += __shfl_xor_sync(0xFFFFFFFFu, z2, d);
            }
            if (p16 == 0) {
                part = fmaf(tanh_f(z2 + fb_c), s_xd[32], part);
                s_f[hg] = part;
                st_peer_f32(u_f + hg * 4, peer, part);
                bar_arrive_peer(barF, peer);
            }
            __syncthreads();
            bar_wait(barF, phF & 1); phF++;
        }
    };

    // --- interval scan + RK4 -----------------------------------------------------
    for (int iv = 0; iv < T_LEN - 1; iv++) {
        float dti = tysb[(iv + 1) * CC] - tysb[iv * CC];
        if (tid < CC) {
            float di = (tysb[(iv + 1) * CC + tid] - tysb[iv * CC + tid]) / dti;
            float d0v;
            if (iv == 0) {
                d0v = di;
            } else {
                float dtm = tysb[iv * CC] - tysb[(iv - 1) * CC];
                d0v = (tysb[iv * CC + tid] - tysb[(iv - 1) * CC + tid]) / dtm;
            }
            float d1v = di;
            s_d0[tid] = d0v;
            s_cc[tid] = (3.f * di - 2.f * d0v - d1v) / dti;
            s_bb[tid] = (d0v + d1v - 2.f * di) / (dti * dti);
        }
        __syncthreads();

        float hsub = dti * 0.25f;
#pragma unroll 1
        for (int sub = 0; sub < 4; sub++) {
            float s0 = hsub * (float)sub;
            vf(s0, s_y);
            if (tid < HID) {
                float k1 = s_f[tid];
                s_ks[tid] = k1;
                s_yt[tid] = fmaf(0.5f * hsub, k1, s_y[tid]);
            }
            __syncthreads();
            vf(s0 + 0.5f * hsub, s_yt);
            if (tid < HID) {
                float k2 = s_f[tid];
                s_ks[tid] += 2.f * k2;
                s_yt[tid] = fmaf(0.5f * hsub, k2, s_y[tid]);
            }
            __syncthreads();
            vf(s0 + 0.5f * hsub, s_yt);
            if (tid < HID) {
                float k3 = s_f[tid];
                s_ks[tid] += 2.f * k3;
                s_yt[tid] = fmaf(hsub, k3, s_y[tid]);
            }
            __syncthreads();
            vf(s0 + hsub, s_yt);
            if (tid < HID) {
                s_y[tid] = fmaf(hsub * (1.f / 6.f), s_ks[tid] + s_f[tid], s_y[tid]);
            }
            __syncthreads();
        }

        if (rank == 0) mvw<2, HID, ACT_NONE>(lW, s_y, lb, out + (size_t)(b * T_LEN + iv + 1) * OBS);
    }

    asm volatile("barrier.cluster.arrive.aligned;" ::: "memory");
    asm volatile("barrier.cluster.wait.aligned;" ::: "memory");
}

// ---------------- launch --------------------------------------------------------
static const int SMEM_BYTES = 16
    + (3 * 64 * WID + 32 * WID) * 4            // half2 hidden weights
    + (32 * CC + NTH + 3 * WID + WID + 2 * WID + 4 * HID + 4 * 36) * 4;

extern "C" void kernel_launch(void* const* d_in, const int* in_sizes, int n_in,
                              void* d_out, int out_size) {
    const float* ts  = (const float*)d_in[0];
    const float* ys  = (const float*)d_in[1];
    const float* iW0 = (const float*)d_in[2];
    const float* ib0 = (const float*)d_in[3];
    const float* iWh = (const float*)d_in[4];
    const float* ibh = (const float*)d_in[5];
    const float* iWo = (const float*)d_in[6];
    const float* ibo = (const float*)d_in[7];
    const float* fW0 = (const float*)d_in[8];
    const float* fb0 = (const float*)d_in[9];
    const float* fWh = (const float*)d_in[10];
    const float* fbh = (const float*)d_in[11];
    const float* fWo = (const float*)d_in[12];
    const float* fbo = (const float*)d_in[13];
    const float* lW  = (const float*)d_in[14];
    const float* lb  = (const float*)d_in[15];
    float* out = (float*)d_out;

    cudaFuncSetAttribute(ncde_main, cudaFuncAttributeMaxDynamicSharedMemorySize, SMEM_BYTES);

    prep_fwo<<<132, 256>>>(fWo);
    prep_h2<<<112, 256>>>(fWh, fW0);
    ncde_main<<<128, NTH, SMEM_BYTES>>>(ts, ys, iW0, ib0, iWh, ibh, iWo, ibo,
                                        fb0, fbh, fbo, lW, lb, out);
}